// round 1
// baseline (speedup 1.0000x reference)
#include <cuda_runtime.h>
#include <cuda_bf16.h>

// Problem constants
#define N_NODES 50000
#define K_EIG   512
#define F_DIM   128

// Scratch for spec = U^T @ x  [K_EIG, F_DIM] (fp32). 256 KB device global.
__device__ float g_spec[K_EIG * F_DIM];

// ---------------------------------------------------------------------------
// Kernel 0: zero the spec scratch (graph replays need re-zeroing every call)
// ---------------------------------------------------------------------------
__global__ void zero_spec_kernel() {
    int idx = blockIdx.x * blockDim.x + threadIdx.x;       // 0 .. 8191
    float4 z = make_float4(0.f, 0.f, 0.f, 0.f);
    // 65536 floats = 16384 float4; grid 64 x 256 threads -> 1 float4 each
    reinterpret_cast<float4*>(g_spec)[idx] = z;
}

// ---------------------------------------------------------------------------
// Kernel 1: spec[k, f] += sum_n U[n, k] * x[n, f]   (split-N, atomic reduce)
//   grid: (K_EIG/64, ceil(N/512)) ; block: 256 threads
//   Each block: 64k x 128f output tile, reduced over a 512-row N chunk.
// ---------------------------------------------------------------------------
__global__ __launch_bounds__(256)
void phase1_kernel(const float* __restrict__ U, const float* __restrict__ X) {
    __shared__ float Us[16][64];     // [n_local][k_local]
    __shared__ float Xs[16][128];    // [n_local][f]

    const int k0 = blockIdx.x * 64;
    const int n0 = blockIdx.y * 512;
    const int n1 = min(n0 + 512, N_NODES);   // N is a multiple of 16

    const int tid = threadIdx.x;
    const int tf  = tid & 15;    // 0..15  -> covers 8 f each
    const int tk  = tid >> 4;    // 0..15  -> covers 4 k each

    float acc[4][8];
#pragma unroll
    for (int i = 0; i < 4; i++)
#pragma unroll
        for (int j = 0; j < 8; j++) acc[i][j] = 0.f;

    for (int n = n0; n < n1; n += 16) {
        // Load U tile: 16 x 64 = 256 float4, one per thread
        {
            int r  = tid >> 4;     // 0..15
            int c4 = tid & 15;     // 0..15
            *reinterpret_cast<float4*>(&Us[r][c4 * 4]) =
                *reinterpret_cast<const float4*>(&U[(size_t)(n + r) * K_EIG + k0 + c4 * 4]);
        }
        // Load X tile: 16 x 128 = 512 float4, two per thread
#pragma unroll
        for (int i = 0; i < 2; i++) {
            int idx = tid + i * 256;
            int r   = idx >> 5;    // 0..15
            int c4  = idx & 31;    // 0..31
            *reinterpret_cast<float4*>(&Xs[r][c4 * 4]) =
                *reinterpret_cast<const float4*>(&X[(size_t)(n + r) * F_DIM + c4 * 4]);
        }
        __syncthreads();

#pragma unroll
        for (int nn = 0; nn < 16; nn++) {
            float4 a  = *reinterpret_cast<float4*>(&Us[nn][tk * 4]);
            float4 b0 = *reinterpret_cast<float4*>(&Xs[nn][tf * 8]);
            float4 b1 = *reinterpret_cast<float4*>(&Xs[nn][tf * 8 + 4]);
            float av[4] = {a.x, a.y, a.z, a.w};
            float bv[8] = {b0.x, b0.y, b0.z, b0.w, b1.x, b1.y, b1.z, b1.w};
#pragma unroll
            for (int i = 0; i < 4; i++)
#pragma unroll
                for (int j = 0; j < 8; j++)
                    acc[i][j] = fmaf(av[i], bv[j], acc[i][j]);
        }
        __syncthreads();
    }

    // Reduce into global spec
#pragma unroll
    for (int i = 0; i < 4; i++) {
        int k = k0 + tk * 4 + i;
#pragma unroll
        for (int j = 0; j < 8; j++) {
            int f = tf * 8 + j;
            atomicAdd(&g_spec[k * F_DIM + f], acc[i][j]);
        }
    }
}

// ---------------------------------------------------------------------------
// Kernel 2: out[n, f] = relu( sum_k U[n, k] * (g[k] * spec[k, f]) )
//   grid: ceil(N/128) ; block: 256 threads ; 128n x 128f tile, 8x8 micro-tile
// ---------------------------------------------------------------------------
__global__ __launch_bounds__(256)
void phase2_kernel(const float* __restrict__ U, const float* __restrict__ g,
                   float* __restrict__ out) {
    // Us transposed: [k_local][n_local], padded row stride 132 (mult of 4)
    __shared__ float Us[16][132];
    __shared__ float Ws[16][128];

    const int n0  = blockIdx.x * 128;
    const int tid = threadIdx.x;
    const int tx  = tid & 15;    // f micro-tile index (8 f each)
    const int ty  = tid >> 4;    // n micro-tile index (8 n each)

    float acc[8][8];
#pragma unroll
    for (int i = 0; i < 8; i++)
#pragma unroll
        for (int j = 0; j < 8; j++) acc[i][j] = 0.f;

    for (int k0 = 0; k0 < K_EIG; k0 += 16) {
        // Load + transpose U tile: 128 rows x 16 k -> Us[k][n]
#pragma unroll
        for (int i = 0; i < 2; i++) {
            int idx = tid + i * 256;
            int r   = idx >> 2;          // n_local 0..127
            int c4  = idx & 3;           // k quad 0..3
            int n   = n0 + r;
            float4 v;
            if (n < N_NODES)
                v = *reinterpret_cast<const float4*>(&U[(size_t)n * K_EIG + k0 + c4 * 4]);
            else
                v = make_float4(0.f, 0.f, 0.f, 0.f);
            Us[c4 * 4 + 0][r] = v.x;
            Us[c4 * 4 + 1][r] = v.y;
            Us[c4 * 4 + 2][r] = v.z;
            Us[c4 * 4 + 3][r] = v.w;
        }
        // Load W tile: Ws[kk][f] = g[k0+kk] * spec[k0+kk][f]
#pragma unroll
        for (int i = 0; i < 2; i++) {
            int idx = tid + i * 256;
            int kk  = idx >> 5;          // 0..15
            int c4  = idx & 31;          // 0..31
            float gv = g[k0 + kk];
            float4 v = *reinterpret_cast<const float4*>(&g_spec[(k0 + kk) * F_DIM + c4 * 4]);
            v.x *= gv; v.y *= gv; v.z *= gv; v.w *= gv;
            *reinterpret_cast<float4*>(&Ws[kk][c4 * 4]) = v;
        }
        __syncthreads();

#pragma unroll
        for (int kk = 0; kk < 16; kk++) {
            float a[8], b[8];
            *reinterpret_cast<float4*>(&a[0]) = *reinterpret_cast<float4*>(&Us[kk][ty * 8]);
            *reinterpret_cast<float4*>(&a[4]) = *reinterpret_cast<float4*>(&Us[kk][ty * 8 + 4]);
            *reinterpret_cast<float4*>(&b[0]) = *reinterpret_cast<float4*>(&Ws[kk][tx * 8]);
            *reinterpret_cast<float4*>(&b[4]) = *reinterpret_cast<float4*>(&Ws[kk][tx * 8 + 4]);
#pragma unroll
            for (int i = 0; i < 8; i++)
#pragma unroll
                for (int j = 0; j < 8; j++)
                    acc[i][j] = fmaf(a[i], b[j], acc[i][j]);
        }
        __syncthreads();
    }

    // Epilogue: relu + store
#pragma unroll
    for (int i = 0; i < 8; i++) {
        int n = n0 + ty * 8 + i;
        if (n < N_NODES) {
            float4 v0, v1;
            v0.x = fmaxf(acc[i][0], 0.f); v0.y = fmaxf(acc[i][1], 0.f);
            v0.z = fmaxf(acc[i][2], 0.f); v0.w = fmaxf(acc[i][3], 0.f);
            v1.x = fmaxf(acc[i][4], 0.f); v1.y = fmaxf(acc[i][5], 0.f);
            v1.z = fmaxf(acc[i][6], 0.f); v1.w = fmaxf(acc[i][7], 0.f);
            float4* o = reinterpret_cast<float4*>(&out[(size_t)n * F_DIM + tx * 8]);
            o[0] = v0;
            o[1] = v1;
        }
    }
}

// ---------------------------------------------------------------------------
// Launch
// ---------------------------------------------------------------------------
extern "C" void kernel_launch(void* const* d_in, const int* in_sizes, int n_in,
                              void* d_out, int out_size) {
    const float* U = (const float*)d_in[0];   // eigenvectors [N, K]
    const float* g = (const float*)d_in[1];   // spectral_filters [K]
    const float* X = (const float*)d_in[2];   // x [N, F]
    float* out = (float*)d_out;               // [N, F]

    zero_spec_kernel<<<64, 256>>>();

    dim3 grid1(K_EIG / 64, (N_NODES + 511) / 512);  // (8, 98)
    phase1_kernel<<<grid1, 256>>>(U, X);

    int grid2 = (N_NODES + 127) / 128;              // 391
    phase2_kernel<<<grid2, 256>>>(U, g, out);
}

// round 6
// speedup vs baseline: 1.9382x; 1.9382x over previous
#include <cuda_runtime.h>
#include <cuda_bf16.h>
#include <cstdint>

#define N_NODES 50000
#define K_EIG   512
#define F_DIM   128

// ---------------- device scratch (no runtime allocation allowed) ----------
__device__ float          g_spec[K_EIG * F_DIM];          // fp32 spec [k][f]
__device__ __nv_bfloat16  g_wt_hi[F_DIM * K_EIG];         // W^T hi  [f][k]
__device__ __nv_bfloat16  g_wt_lo[F_DIM * K_EIG];         // W^T lo  [f][k]

// ---------------- helpers --------------------------------------------------
static __device__ __forceinline__ uint32_t smem_u32(const void* p) {
    uint32_t a;
    asm("{ .reg .u64 t; cvta.to.shared.u64 t, %1; cvt.u32.u64 %0, t; }" : "=r"(a) : "l"(p));
    return a;
}

#define LDSM_X4(r0, r1, r2, r3, addr) \
    asm volatile("ldmatrix.sync.aligned.m8n8.x4.shared.b16 {%0,%1,%2,%3}, [%4];" \
        : "=r"(r0), "=r"(r1), "=r"(r2), "=r"(r3) : "r"(addr))

#define MMA_BF16(c0, c1, c2, c3, a0, a1, a2, a3, b0, b1) \
    asm volatile("mma.sync.aligned.m16n8k16.row.col.f32.bf16.bf16.f32 " \
        "{%0,%1,%2,%3}, {%4,%5,%6,%7}, {%8,%9}, {%0,%1,%2,%3};" \
        : "+f"(c0), "+f"(c1), "+f"(c2), "+f"(c3) \
        : "r"(a0), "r"(a1), "r"(a2), "r"(a3), "r"(b0), "r"(b1))

static __device__ __forceinline__ uint32_t pack_bf2(__nv_bfloat16 a, __nv_bfloat16 b) {
    __nv_bfloat162 t; t.x = a; t.y = b;
    return *reinterpret_cast<uint32_t*>(&t);
}
static __device__ __forceinline__ void split_bf16(float f, __nv_bfloat16& h, __nv_bfloat16& l) {
    h = __float2bfloat16(f);
    l = __float2bfloat16(f - __bfloat162float(h));
}

// ---------------- smem layout ----------------------------------------------
// Tiles: [128 rows][64 contraction cols] bf16, row stride 144B (128B data + 16 pad).
// stride 144 => row n starts at bank (4n mod 32): conflict-free ldmatrix & STS.128.
#define TSTRIDE 144
#define OFF_AHI 0
#define OFF_ALO (128 * TSTRIDE)
#define OFF_BHI (2 * 128 * TSTRIDE)
#define OFF_BLO (3 * 128 * TSTRIDE)
#define SMEM_BYTES (4 * 128 * TSTRIDE)   // 73728

#define P1_ITERS  22
#define P1_CHUNK  (P1_ITERS * 64)        // 1408
#define P1_CHUNKS 37                     // 37*1408 = 52096 >= 50000

// ---------------------------------------------------------------------------
// Kernel 0: zero spec scratch
// ---------------------------------------------------------------------------
__global__ void zero_spec_kernel() {
    int idx = blockIdx.x * blockDim.x + threadIdx.x;
    reinterpret_cast<float4*>(g_spec)[idx] = make_float4(0.f, 0.f, 0.f, 0.f);
}

// ---------------------------------------------------------------------------
// Warp-level 128x128 mainloop body (shared by both phases).
// A tile rows = output-m dim, B tile rows = output-n dim, cols = contraction.
// ---------------------------------------------------------------------------
static __device__ __forceinline__ void warp_mma_64(
    const uint32_t sb, const int wm, const int wf, const int lane,
    float c[2][8][4])
{
#pragma unroll
    for (int ks = 0; ks < 4; ks++) {
        const uint32_t colb = ks * 32;
        // A fragments (hi & lo), 2 x m16
        uint32_t ahi[2][4], alo[2][4];
#pragma unroll
        for (int mi = 0; mi < 2; mi++) {
            const uint32_t row = wm * 32 + mi * 16 + (lane & 7) + ((lane >> 3) & 1) * 8;
            const uint32_t off = row * TSTRIDE + colb + (lane >> 4) * 16;
            LDSM_X4(ahi[mi][0], ahi[mi][1], ahi[mi][2], ahi[mi][3], sb + OFF_AHI + off);
            LDSM_X4(alo[mi][0], alo[mi][1], alo[mi][2], alo[mi][3], sb + OFF_ALO + off);
        }
        // B fragment pairs: each x4 covers n-groups (2gp, 2gp+1)
#pragma unroll
        for (int gp = 0; gp < 4; gp++) {
            const uint32_t row = wf * 64 + gp * 16 + (lane & 7) + ((lane >> 4) & 1) * 8;
            const uint32_t off = row * TSTRIDE + colb + ((lane >> 3) & 1) * 16;
            uint32_t bh[4], bl[4];
            LDSM_X4(bh[0], bh[1], bh[2], bh[3], sb + OFF_BHI + off);
            LDSM_X4(bl[0], bl[1], bl[2], bl[3], sb + OFF_BLO + off);
#pragma unroll
            for (int mi = 0; mi < 2; mi++) {
#pragma unroll
                for (int gg = 0; gg < 2; gg++) {
                    float* cc = c[mi][gp * 2 + gg];
                    MMA_BF16(cc[0], cc[1], cc[2], cc[3],
                             ahi[mi][0], ahi[mi][1], ahi[mi][2], ahi[mi][3],
                             bh[gg * 2], bh[gg * 2 + 1]);
                    MMA_BF16(cc[0], cc[1], cc[2], cc[3],
                             ahi[mi][0], ahi[mi][1], ahi[mi][2], ahi[mi][3],
                             bl[gg * 2], bl[gg * 2 + 1]);
                    MMA_BF16(cc[0], cc[1], cc[2], cc[3],
                             alo[mi][0], alo[mi][1], alo[mi][2], alo[mi][3],
                             bh[gg * 2], bh[gg * 2 + 1]);
                }
            }
        }
    }
}

// ---------------------------------------------------------------------------
// Kernel 1: spec[k,f] += sum_n U[n,k]*x[n,f]
// A tile [k=128][node=64] (transposed in STS), B tile [f=128][node=64].
// ---------------------------------------------------------------------------
__global__ __launch_bounds__(256)
void phase1_mma(const float* __restrict__ U, const float* __restrict__ X) {
    extern __shared__ char smem[];
    const uint32_t sb = smem_u32(smem);
    const int tid = threadIdx.x, wid = tid >> 5, lane = tid & 31;
    const int wm = wid >> 1, wf = wid & 1;

    const int k0    = blockIdx.x * 128;
    const int nbase = blockIdx.y * P1_CHUNK;

    float c[2][8][4];
#pragma unroll
    for (int mi = 0; mi < 2; mi++)
#pragma unroll
        for (int g = 0; g < 8; g++)
#pragma unroll
            for (int r = 0; r < 4; r++) c[mi][g][r] = 0.f;

    for (int it = 0; it < P1_ITERS; it++) {
        const int n0 = nbase + it * 64;
        // 512 tasks per operand: (16 node-quads) x (32 row-quads); 2 per thread
        // each task writes 4 rows x 4 cols for A and B -> full 128x64 coverage
#pragma unroll
        for (int ph = 0; ph < 2; ph++) {
            const int task = tid + ph * 256;
            const int nq = task & 15;       // node quad (4 nodes)
            const int rq = task >> 4;       // row quad (4 rows of A/B tile)
            float4 vu[4], vx[4];
#pragma unroll
            for (int j4 = 0; j4 < 4; j4++) {
                const int node = n0 + nq * 4 + j4;
                if (node < N_NODES) {
                    vu[j4] = *reinterpret_cast<const float4*>(U + (size_t)node * K_EIG + k0 + rq * 4);
                    vx[j4] = *reinterpret_cast<const float4*>(X + (size_t)node * F_DIM + rq * 4);
                } else {
                    vu[j4] = make_float4(0.f, 0.f, 0.f, 0.f);
                    vx[j4] = make_float4(0.f, 0.f, 0.f, 0.f);
                }
            }
#pragma unroll
            for (int j = 0; j < 4; j++) {       // row = rq*4+j, col = node
                const uint32_t off = (uint32_t)(rq * 4 + j) * TSTRIDE + nq * 8;
                __nv_bfloat16 h0, l0, h1, l1, h2, l2, h3, l3;
                split_bf16((&vu[0].x)[j], h0, l0);
                split_bf16((&vu[1].x)[j], h1, l1);
                split_bf16((&vu[2].x)[j], h2, l2);
                split_bf16((&vu[3].x)[j], h3, l3);
                *reinterpret_cast<uint2*>(smem + OFF_AHI + off) =
                    make_uint2(pack_bf2(h0, h1), pack_bf2(h2, h3));
                *reinterpret_cast<uint2*>(smem + OFF_ALO + off) =
                    make_uint2(pack_bf2(l0, l1), pack_bf2(l2, l3));
                split_bf16((&vx[0].x)[j], h0, l0);
                split_bf16((&vx[1].x)[j], h1, l1);
                split_bf16((&vx[2].x)[j], h2, l2);
                split_bf16((&vx[3].x)[j], h3, l3);
                *reinterpret_cast<uint2*>(smem + OFF_BHI + off) =
                    make_uint2(pack_bf2(h0, h1), pack_bf2(h2, h3));
                *reinterpret_cast<uint2*>(smem + OFF_BLO + off) =
                    make_uint2(pack_bf2(l0, l1), pack_bf2(l2, l3));
            }
        }
        __syncthreads();
        warp_mma_64(sb, wm, wf, lane, c);
        __syncthreads();
    }

    // reduce into g_spec
#pragma unroll
    for (int mi = 0; mi < 2; mi++) {
        const int k = k0 + wm * 32 + mi * 16 + (lane >> 2);
#pragma unroll
        for (int g = 0; g < 8; g++) {
            const int f = wf * 64 + g * 8 + (lane & 3) * 2;
            atomicAdd(&g_spec[k * F_DIM + f],           c[mi][g][0]);
            atomicAdd(&g_spec[k * F_DIM + f + 1],       c[mi][g][1]);
            atomicAdd(&g_spec[(k + 8) * F_DIM + f],     c[mi][g][2]);
            atomicAdd(&g_spec[(k + 8) * F_DIM + f + 1], c[mi][g][3]);
        }
    }
}

// ---------------------------------------------------------------------------
// Kernel 1.5: Wt[f][k] = split_bf16( g[k] * spec[k][f] )
// ---------------------------------------------------------------------------
__global__ void transpose_scale_kernel(const float* __restrict__ g) {
    __shared__ float tile[32][33];
    const int k0 = blockIdx.x * 32, f0 = blockIdx.y * 32;
    const int tx = threadIdx.x, ty = threadIdx.y;
#pragma unroll
    for (int i = 0; i < 4; i++) {
        const int k = k0 + ty + 8 * i;
        tile[ty + 8 * i][tx] = g_spec[k * F_DIM + f0 + tx] * g[k];
    }
    __syncthreads();
#pragma unroll
    for (int i = 0; i < 4; i++) {
        const int f = f0 + ty + 8 * i;
        const int k = k0 + tx;
        const float v = tile[tx][ty + 8 * i];
        __nv_bfloat16 h = __float2bfloat16(v);
        g_wt_hi[f * K_EIG + k] = h;
        g_wt_lo[f * K_EIG + k] = __float2bfloat16(v - __bfloat162float(h));
    }
}

// ---------------------------------------------------------------------------
// Kernel 2: out[n,f] = relu( sum_k U[n,k] * Wt[f,k] )
// A tile [node=128][k=64] (natural), B tile [f=128][k=64] (natural bf16).
// ---------------------------------------------------------------------------
__global__ __launch_bounds__(256)
void phase2_mma(const float* __restrict__ U, float* __restrict__ out) {
    extern __shared__ char smem[];
    const uint32_t sb = smem_u32(smem);
    const int tid = threadIdx.x, wid = tid >> 5, lane = tid & 31;
    const int wm = wid >> 1, wf = wid & 1;

    const int n0 = blockIdx.x * 128;

    float c[2][8][4];
#pragma unroll
    for (int mi = 0; mi < 2; mi++)
#pragma unroll
        for (int g = 0; g < 8; g++)
#pragma unroll
            for (int r = 0; r < 4; r++) c[mi][g][r] = 0.f;

    for (int kc = 0; kc < K_EIG; kc += 64) {
        // A & B: 1024 16B tasks each -> full 128 rows x 128 bytes coverage.
        // task: row = task & 127 (tile row), k8 = task >> 7 in 0..7 (8-elem k group)
#pragma unroll
        for (int ph = 0; ph < 4; ph++) {
            const int task = tid + ph * 256;
            const int row = task & 127;     // node row (A) / f row (B)
            const int k8  = task >> 7;      // 0..7
            const int node = n0 + row;
            float4 v0, v1;
            if (node < N_NODES) {
                const float* p = U + (size_t)node * K_EIG + kc + k8 * 8;
                v0 = *reinterpret_cast<const float4*>(p);
                v1 = *reinterpret_cast<const float4*>(p + 4);
            } else {
                v0 = make_float4(0.f, 0.f, 0.f, 0.f);
                v1 = v0;
            }
            __nv_bfloat16 h[8], l[8];
            split_bf16(v0.x, h[0], l[0]); split_bf16(v0.y, h[1], l[1]);
            split_bf16(v0.z, h[2], l[2]); split_bf16(v0.w, h[3], l[3]);
            split_bf16(v1.x, h[4], l[4]); split_bf16(v1.y, h[5], l[5]);
            split_bf16(v1.z, h[6], l[6]); split_bf16(v1.w, h[7], l[7]);
            const uint32_t off = (uint32_t)row * TSTRIDE + k8 * 16;
            *reinterpret_cast<uint4*>(smem + OFF_AHI + off) =
                make_uint4(pack_bf2(h[0], h[1]), pack_bf2(h[2], h[3]),
                           pack_bf2(h[4], h[5]), pack_bf2(h[6], h[7]));
            *reinterpret_cast<uint4*>(smem + OFF_ALO + off) =
                make_uint4(pack_bf2(l[0], l[1]), pack_bf2(l[2], l[3]),
                           pack_bf2(l[4], l[5]), pack_bf2(l[6], l[7]));
            // B: Wt hi/lo already bf16, straight copy (row = f here)
            const uint4 bh = *reinterpret_cast<const uint4*>(g_wt_hi + row * K_EIG + kc + k8 * 8);
            const uint4 bl = *reinterpret_cast<const uint4*>(g_wt_lo + row * K_EIG + kc + k8 * 8);
            *reinterpret_cast<uint4*>(smem + OFF_BHI + off) = bh;
            *reinterpret_cast<uint4*>(smem + OFF_BLO + off) = bl;
        }
        __syncthreads();
        warp_mma_64(sb, wm, wf, lane, c);
        __syncthreads();
    }

    // relu + store
#pragma unroll
    for (int mi = 0; mi < 2; mi++) {
        const int node = n0 + wm * 32 + mi * 16 + (lane >> 2);
#pragma unroll
        for (int g = 0; g < 8; g++) {
            const int f = wf * 64 + g * 8 + (lane & 3) * 2;
            if (node < N_NODES) {
                float2 v0;
                v0.x = fmaxf(c[mi][g][0], 0.f);
                v0.y = fmaxf(c[mi][g][1], 0.f);
                *reinterpret_cast<float2*>(out + (size_t)node * F_DIM + f) = v0;
            }
            if (node + 8 < N_NODES) {
                float2 v1;
                v1.x = fmaxf(c[mi][g][2], 0.f);
                v1.y = fmaxf(c[mi][g][3], 0.f);
                *reinterpret_cast<float2*>(out + (size_t)(node + 8) * F_DIM + f) = v1;
            }
        }
    }
}

// ---------------------------------------------------------------------------
// Launch
// ---------------------------------------------------------------------------
extern "C" void kernel_launch(void* const* d_in, const int* in_sizes, int n_in,
                              void* d_out, int out_size) {
    const float* U = (const float*)d_in[0];   // eigenvectors [N, K]
    const float* g = (const float*)d_in[1];   // spectral_filters [K]
    const float* X = (const float*)d_in[2];   // x [N, F]
    float* out = (float*)d_out;               // [N, F]

    cudaFuncSetAttribute(phase1_mma, cudaFuncAttributeMaxDynamicSharedMemorySize, SMEM_BYTES);
    cudaFuncSetAttribute(phase2_mma, cudaFuncAttributeMaxDynamicSharedMemorySize, SMEM_BYTES);

    zero_spec_kernel<<<64, 256>>>();

    phase1_mma<<<dim3(4, P1_CHUNKS), 256, SMEM_BYTES>>>(U, X);

    transpose_scale_kernel<<<dim3(K_EIG / 32, F_DIM / 32), dim3(32, 8)>>>(g);

    phase2_mma<<<(N_NODES + 127) / 128, 256, SMEM_BYTES>>>(U, out);
}

// round 7
// speedup vs baseline: 3.0431x; 1.5700x over previous
#include <cuda_runtime.h>
#include <cuda_bf16.h>
#include <cstdint>

#define N_NODES 50000
#define K_EIG   512
#define F_DIM   128

// ---------------- device scratch (static; no runtime allocation) ----------
__device__ float          g_spec[K_EIG * F_DIM];             // fp32 spec [k][f]
__device__ __nv_bfloat16  g_wt_hi[F_DIM * K_EIG];            // W^T hi [f][k]
__device__ __nv_bfloat16  g_wt_lo[F_DIM * K_EIG];            // W^T lo [f][k]
__device__ __nv_bfloat16  g_u_hi[(size_t)N_NODES * K_EIG];   // U hi [n][k]
__device__ __nv_bfloat16  g_u_lo[(size_t)N_NODES * K_EIG];   // U lo [n][k]
__device__ __nv_bfloat16  g_x_hi[(size_t)N_NODES * F_DIM];   // X hi [n][f]
__device__ __nv_bfloat16  g_x_lo[(size_t)N_NODES * F_DIM];   // X lo [n][f]

// ---------------- helpers --------------------------------------------------
static __device__ __forceinline__ uint32_t smem_u32(const void* p) {
    uint32_t a;
    asm("{ .reg .u64 t; cvta.to.shared.u64 t, %1; cvt.u32.u64 %0, t; }" : "=r"(a) : "l"(p));
    return a;
}

#define LDSM_X4(r0, r1, r2, r3, addr) \
    asm volatile("ldmatrix.sync.aligned.m8n8.x4.shared.b16 {%0,%1,%2,%3}, [%4];" \
        : "=r"(r0), "=r"(r1), "=r"(r2), "=r"(r3) : "r"(addr))

#define LDSM_X4_T(r0, r1, r2, r3, addr) \
    asm volatile("ldmatrix.sync.aligned.m8n8.x4.trans.shared.b16 {%0,%1,%2,%3}, [%4];" \
        : "=r"(r0), "=r"(r1), "=r"(r2), "=r"(r3) : "r"(addr))

#define MMA_BF16(c0, c1, c2, c3, a0, a1, a2, a3, b0, b1) \
    asm volatile("mma.sync.aligned.m16n8k16.row.col.f32.bf16.bf16.f32 " \
        "{%0,%1,%2,%3}, {%4,%5,%6,%7}, {%8,%9}, {%0,%1,%2,%3};" \
        : "+f"(c0), "+f"(c1), "+f"(c2), "+f"(c3) \
        : "r"(a0), "r"(a1), "r"(a2), "r"(a3), "r"(b0), "r"(b1))

static __device__ __forceinline__ void cp16(uint32_t dst, const void* src, int sz) {
    asm volatile("cp.async.cg.shared.global [%0], [%1], 16, %2;"
                 :: "r"(dst), "l"(src), "r"(sz));
}
#define CP_COMMIT() asm volatile("cp.async.commit_group;" ::: "memory")
#define CP_WAIT1()  asm volatile("cp.async.wait_group 1;"  ::: "memory")
#define CP_WAIT0()  asm volatile("cp.async.wait_group 0;"  ::: "memory")

static __device__ __forceinline__ uint32_t pack_bf2(__nv_bfloat16 a, __nv_bfloat16 b) {
    __nv_bfloat162 t; t.x = a; t.y = b;
    return *reinterpret_cast<uint32_t*>(&t);
}
static __device__ __forceinline__ void split_bf16(float f, __nv_bfloat16& h, __nv_bfloat16& l) {
    h = __float2bfloat16(f);
    l = __float2bfloat16(f - __bfloat162float(h));
}

// ---------------- geometry -------------------------------------------------
// phase1 tiles: [32 node rows][128 cols] bf16, stride 272B (256 data + 16 pad)
#define S1 272
#define T1 (32 * S1)     // 8704
#define B1 (4 * T1)      // 34816: Uhi, Ulo, Xhi, Xlo
#define SMEM1 (2 * B1)   // 69632
#define P1_ITERS  22
#define P1_CHUNK  (P1_ITERS * 32)   // 704
#define P1_CHUNKS 72                // 4 x 72 = 288 CTAs (one wave @ 2/SM)

// phase2 tiles: [128 rows][32 k cols] bf16, stride 80B (64 data + 16 pad)
#define S2 80
#define T2 (128 * S2)    // 10240
#define B2 (4 * T2)      // 40960: Ahi, Alo, Bhi, Blo
#define SMEM2 (2 * B2)   // 81920
#define NIT2 (K_EIG / 32)  // 16

// ---------------------------------------------------------------------------
// Kernel 0: zero spec scratch (graph replays re-zero every call)
// ---------------------------------------------------------------------------
__global__ void zero_spec_kernel() {
    int idx = blockIdx.x * blockDim.x + threadIdx.x;
    reinterpret_cast<float4*>(g_spec)[idx] = make_float4(0.f, 0.f, 0.f, 0.f);
}

// ---------------------------------------------------------------------------
// Kernel S: split U and X into hi/lo bf16 (one bandwidth pass)
// thread handles 8 consecutive floats -> one 16B hi store + one 16B lo store
// ---------------------------------------------------------------------------
__global__ __launch_bounds__(256)
void split_kernel(const float* __restrict__ U, const float* __restrict__ X) {
    const size_t gid = (size_t)blockIdx.x * 256 + threadIdx.x;
    const size_t UN = (size_t)N_NODES * K_EIG / 8;   // 3,200,000
    const float* src;
    __nv_bfloat16 *dhi, *dlo;
    size_t e;
    if (gid < UN) {
        e = gid * 8;
        src = U + e; dhi = g_u_hi + e; dlo = g_u_lo + e;
    } else {
        e = (gid - UN) * 8;                          // < 6,400,000
        src = X + e; dhi = g_x_hi + e; dlo = g_x_lo + e;
    }
    float4 v0 = *reinterpret_cast<const float4*>(src);
    float4 v1 = *reinterpret_cast<const float4*>(src + 4);
    __nv_bfloat16 h[8], l[8];
    split_bf16(v0.x, h[0], l[0]); split_bf16(v0.y, h[1], l[1]);
    split_bf16(v0.z, h[2], l[2]); split_bf16(v0.w, h[3], l[3]);
    split_bf16(v1.x, h[4], l[4]); split_bf16(v1.y, h[5], l[5]);
    split_bf16(v1.z, h[6], l[6]); split_bf16(v1.w, h[7], l[7]);
    *reinterpret_cast<uint4*>(dhi) =
        make_uint4(pack_bf2(h[0], h[1]), pack_bf2(h[2], h[3]),
                   pack_bf2(h[4], h[5]), pack_bf2(h[6], h[7]));
    *reinterpret_cast<uint4*>(dlo) =
        make_uint4(pack_bf2(l[0], l[1]), pack_bf2(l[2], l[3]),
                   pack_bf2(l[4], l[5]), pack_bf2(l[6], l[7]));
}

// ---------------------------------------------------------------------------
// Phase 1: spec[k,f] += sum_n U[n,k]*x[n,f]
// smem tiles natural [node][k] / [node][f]; fragments via ldmatrix.trans.
// ---------------------------------------------------------------------------
static __device__ __forceinline__ void p1_issue(uint32_t sb, int buf, int tid,
                                                int k0, int nodebase) {
#pragma unroll
    for (int t = 0; t < 8; t++) {
        const int seg = tid + t * 256;       // 0..2047
        const int tile = seg >> 9;           // 0:Uhi 1:Ulo 2:Xhi 3:Xlo (uniform per t)
        const int s = seg & 511;
        const int row = s >> 4, sc = s & 15; // 32 rows x 16 segs of 16B
        const uint32_t dst = sb + buf * B1 + tile * T1 + (uint32_t)row * S1 + sc * 16;
        const int node = nodebase + row;
        const __nv_bfloat16* src;
        if (tile == 0)      src = g_u_hi + (size_t)node * K_EIG + k0 + sc * 8;
        else if (tile == 1) src = g_u_lo + (size_t)node * K_EIG + k0 + sc * 8;
        else if (tile == 2) src = g_x_hi + (size_t)node * F_DIM + sc * 8;
        else                src = g_x_lo + (size_t)node * F_DIM + sc * 8;
        int sz = 16;
        if (node >= N_NODES) { sz = 0; src = g_u_hi; }
        cp16(dst, src, sz);
    }
    CP_COMMIT();
}

static __device__ __forceinline__ void p1_mma(uint32_t base, int wm, int wf,
                                              int lane, float c[2][8][4]) {
#pragma unroll
    for (int ks = 0; ks < 2; ks++) {         // contraction 32 nodes = 2 x kk16
        uint32_t ahi[2][4], alo[2][4];
#pragma unroll
        for (int mi = 0; mi < 2; mi++) {
            const uint32_t row = ks * 16 + (lane & 7) + ((lane >> 4) & 1) * 8;  // node
            const uint32_t col = (wm * 32 + mi * 16 + ((lane >> 3) & 1) * 8) * 2; // k bytes
            const uint32_t off = row * S1 + col;
            LDSM_X4_T(ahi[mi][0], ahi[mi][1], ahi[mi][2], ahi[mi][3], base + 0 * T1 + off);
            LDSM_X4_T(alo[mi][0], alo[mi][1], alo[mi][2], alo[mi][3], base + 1 * T1 + off);
        }
#pragma unroll
        for (int gp = 0; gp < 4; gp++) {
            const uint32_t row = ks * 16 + (lane & 7) + ((lane >> 3) & 1) * 8;  // node
            const uint32_t col = (wf * 64 + gp * 16 + ((lane >> 4) & 1) * 8) * 2; // f bytes
            const uint32_t off = row * S1 + col;
            uint32_t bh[4], bl[4];
            LDSM_X4_T(bh[0], bh[1], bh[2], bh[3], base + 2 * T1 + off);
            LDSM_X4_T(bl[0], bl[1], bl[2], bl[3], base + 3 * T1 + off);
#pragma unroll
            for (int mi = 0; mi < 2; mi++) {
#pragma unroll
                for (int gg = 0; gg < 2; gg++) {
                    float* cc = c[mi][gp * 2 + gg];
                    MMA_BF16(cc[0], cc[1], cc[2], cc[3],
                             ahi[mi][0], ahi[mi][1], ahi[mi][2], ahi[mi][3],
                             bh[gg * 2], bh[gg * 2 + 1]);
                    MMA_BF16(cc[0], cc[1], cc[2], cc[3],
                             ahi[mi][0], ahi[mi][1], ahi[mi][2], ahi[mi][3],
                             bl[gg * 2], bl[gg * 2 + 1]);
                    MMA_BF16(cc[0], cc[1], cc[2], cc[3],
                             alo[mi][0], alo[mi][1], alo[mi][2], alo[mi][3],
                             bh[gg * 2], bh[gg * 2 + 1]);
                }
            }
        }
    }
}

__global__ __launch_bounds__(256, 2)
void phase1_mma() {
    extern __shared__ char smem[];
    const uint32_t sb = smem_u32(smem);
    const int tid = threadIdx.x, wid = tid >> 5, lane = tid & 31;
    const int wm = wid >> 1, wf = wid & 1;

    const int k0    = blockIdx.x * 128;
    const int nbase = blockIdx.y * P1_CHUNK;

    float c[2][8][4];
#pragma unroll
    for (int mi = 0; mi < 2; mi++)
#pragma unroll
        for (int g = 0; g < 8; g++)
#pragma unroll
            for (int r = 0; r < 4; r++) c[mi][g][r] = 0.f;

    p1_issue(sb, 0, tid, k0, nbase);
    for (int it = 0; it < P1_ITERS; it++) {
        if (it + 1 < P1_ITERS) {
            p1_issue(sb, (it + 1) & 1, tid, k0, nbase + (it + 1) * 32);
            CP_WAIT1();
        } else {
            CP_WAIT0();
        }
        __syncthreads();
        p1_mma(sb + (it & 1) * B1, wm, wf, lane, c);
        __syncthreads();
    }

    // reduce into g_spec
#pragma unroll
    for (int mi = 0; mi < 2; mi++) {
        const int k = k0 + wm * 32 + mi * 16 + (lane >> 2);
#pragma unroll
        for (int g = 0; g < 8; g++) {
            const int f = wf * 64 + g * 8 + (lane & 3) * 2;
            atomicAdd(&g_spec[k * F_DIM + f],           c[mi][g][0]);
            atomicAdd(&g_spec[k * F_DIM + f + 1],       c[mi][g][1]);
            atomicAdd(&g_spec[(k + 8) * F_DIM + f],     c[mi][g][2]);
            atomicAdd(&g_spec[(k + 8) * F_DIM + f + 1], c[mi][g][3]);
        }
    }
}

// ---------------------------------------------------------------------------
// Kernel 1.5: Wt[f][k] = split_bf16( g[k] * spec[k][f] )
// ---------------------------------------------------------------------------
__global__ void transpose_scale_kernel(const float* __restrict__ g) {
    __shared__ float tile[32][33];
    const int k0 = blockIdx.x * 32, f0 = blockIdx.y * 32;
    const int tx = threadIdx.x, ty = threadIdx.y;
#pragma unroll
    for (int i = 0; i < 4; i++) {
        const int k = k0 + ty + 8 * i;
        tile[ty + 8 * i][tx] = g_spec[k * F_DIM + f0 + tx] * g[k];
    }
    __syncthreads();
#pragma unroll
    for (int i = 0; i < 4; i++) {
        const int f = f0 + ty + 8 * i;
        const int k = k0 + tx;
        const float v = tile[tx][ty + 8 * i];
        __nv_bfloat16 h = __float2bfloat16(v);
        g_wt_hi[f * K_EIG + k] = h;
        g_wt_lo[f * K_EIG + k] = __float2bfloat16(v - __bfloat162float(h));
    }
}

// ---------------------------------------------------------------------------
// Phase 2: out[n,f] = relu( sum_k U[n,k] * Wt[f,k] )  — K-major, non-trans.
// ---------------------------------------------------------------------------
static __device__ __forceinline__ void p2_issue(uint32_t sb, int buf, int tid,
                                                int n0, int kc) {
#pragma unroll
    for (int t = 0; t < 8; t++) {
        const int seg = tid + t * 256;       // 0..2047
        const int tile = seg >> 9;           // 0:Ahi 1:Alo 2:Bhi 3:Blo
        const int s = seg & 511;
        const int row = s >> 2, sc = s & 3;  // 128 rows x 4 segs of 16B
        const uint32_t dst = sb + buf * B2 + tile * T2 + (uint32_t)row * S2 + sc * 16;
        const __nv_bfloat16* src;
        int sz = 16;
        if (tile < 2) {
            const int node = n0 + row;
            src = (tile == 0 ? g_u_hi : g_u_lo) + (size_t)node * K_EIG + kc + sc * 8;
            if (node >= N_NODES) { sz = 0; src = g_u_hi; }
        } else {
            src = (tile == 2 ? g_wt_hi : g_wt_lo) + (size_t)row * K_EIG + kc + sc * 8;
        }
        cp16(dst, src, sz);
    }
    CP_COMMIT();
}

static __device__ __forceinline__ void p2_mma(uint32_t base, int wm, int wf,
                                              int lane, float c[2][8][4]) {
#pragma unroll
    for (int ks = 0; ks < 2; ks++) {         // contraction 32 k = 2 x kk16
        uint32_t ahi[2][4], alo[2][4];
#pragma unroll
        for (int mi = 0; mi < 2; mi++) {
            const uint32_t row = wm * 32 + mi * 16 + (lane & 7) + ((lane >> 3) & 1) * 8;
            const uint32_t off = row * S2 + ks * 32 + (lane >> 4) * 16;
            LDSM_X4(ahi[mi][0], ahi[mi][1], ahi[mi][2], ahi[mi][3], base + 0 * T2 + off);
            LDSM_X4(alo[mi][0], alo[mi][1], alo[mi][2], alo[mi][3], base + 1 * T2 + off);
        }
#pragma unroll
        for (int gp = 0; gp < 4; gp++) {
            const uint32_t row = wf * 64 + gp * 16 + (lane & 7) + ((lane >> 4) & 1) * 8;
            const uint32_t off = row * S2 + ks * 32 + ((lane >> 3) & 1) * 16;
            uint32_t bh[4], bl[4];
            LDSM_X4(bh[0], bh[1], bh[2], bh[3], base + 2 * T2 + off);
            LDSM_X4(bl[0], bl[1], bl[2], bl[3], base + 3 * T2 + off);
#pragma unroll
            for (int mi = 0; mi < 2; mi++) {
#pragma unroll
                for (int gg = 0; gg < 2; gg++) {
                    float* cc = c[mi][gp * 2 + gg];
                    MMA_BF16(cc[0], cc[1], cc[2], cc[3],
                             ahi[mi][0], ahi[mi][1], ahi[mi][2], ahi[mi][3],
                             bh[gg * 2], bh[gg * 2 + 1]);
                    MMA_BF16(cc[0], cc[1], cc[2], cc[3],
                             ahi[mi][0], ahi[mi][1], ahi[mi][2], ahi[mi][3],
                             bl[gg * 2], bl[gg * 2 + 1]);
                    MMA_BF16(cc[0], cc[1], cc[2], cc[3],
                             alo[mi][0], alo[mi][1], alo[mi][2], alo[mi][3],
                             bh[gg * 2], bh[gg * 2 + 1]);
                }
            }
        }
    }
}

__global__ __launch_bounds__(256, 2)
void phase2_mma(float* __restrict__ out) {
    extern __shared__ char smem[];
    const uint32_t sb = smem_u32(smem);
    const int tid = threadIdx.x, wid = tid >> 5, lane = tid & 31;
    const int wm = wid >> 1, wf = wid & 1;

    const int n0 = blockIdx.x * 128;

    float c[2][8][4];
#pragma unroll
    for (int mi = 0; mi < 2; mi++)
#pragma unroll
        for (int g = 0; g < 8; g++)
#pragma unroll
            for (int r = 0; r < 4; r++) c[mi][g][r] = 0.f;

    p2_issue(sb, 0, tid, n0, 0);
    for (int it = 0; it < NIT2; it++) {
        if (it + 1 < NIT2) {
            p2_issue(sb, (it + 1) & 1, tid, n0, (it + 1) * 32);
            CP_WAIT1();
        } else {
            CP_WAIT0();
        }
        __syncthreads();
        p2_mma(sb + (it & 1) * B2, wm, wf, lane, c);
        __syncthreads();
    }

    // relu + store
#pragma unroll
    for (int mi = 0; mi < 2; mi++) {
        const int node = n0 + wm * 32 + mi * 16 + (lane >> 2);
#pragma unroll
        for (int g = 0; g < 8; g++) {
            const int f = wf * 64 + g * 8 + (lane & 3) * 2;
            if (node < N_NODES) {
                float2 v0;
                v0.x = fmaxf(c[mi][g][0], 0.f);
                v0.y = fmaxf(c[mi][g][1], 0.f);
                *reinterpret_cast<float2*>(out + (size_t)node * F_DIM + f) = v0;
            }
            if (node + 8 < N_NODES) {
                float2 v1;
                v1.x = fmaxf(c[mi][g][2], 0.f);
                v1.y = fmaxf(c[mi][g][3], 0.f);
                *reinterpret_cast<float2*>(out + (size_t)(node + 8) * F_DIM + f) = v1;
            }
        }
    }
}

// ---------------------------------------------------------------------------
// Launch
// ---------------------------------------------------------------------------
extern "C" void kernel_launch(void* const* d_in, const int* in_sizes, int n_in,
                              void* d_out, int out_size) {
    const float* U = (const float*)d_in[0];   // eigenvectors [N, K]
    const float* g = (const float*)d_in[1];   // spectral_filters [K]
    const float* X = (const float*)d_in[2];   // x [N, F]
    float* out = (float*)d_out;               // [N, F]

    cudaFuncSetAttribute(phase1_mma, cudaFuncAttributeMaxDynamicSharedMemorySize, SMEM1);
    cudaFuncSetAttribute(phase2_mma, cudaFuncAttributeMaxDynamicSharedMemorySize, SMEM2);

    zero_spec_kernel<<<64, 256>>>();

    // (N*K + N*F)/8 threads = 4,000,000 -> 15625 blocks of 256
    split_kernel<<<15625, 256>>>(U, X);

    phase1_mma<<<dim3(4, P1_CHUNKS), 256, SMEM1>>>();

    transpose_scale_kernel<<<dim3(K_EIG / 32, F_DIM / 32), dim3(32, 8)>>>(g);

    phase2_mma<<<(N_NODES + 127) / 128, 256, SMEM2>>>(out);
}

// round 9
// speedup vs baseline: 3.2821x; 1.0785x over previous
#include <cuda_runtime.h>
#include <cuda_bf16.h>
#include <cstdint>

#define N_NODES 50000
#define K_EIG   512
#define F_DIM   128

// ---------------- device scratch (static; no runtime allocation) ----------
__device__ float          g_spec[K_EIG * F_DIM];             // fp32 spec [k][f]
__device__ __nv_bfloat16  g_wt_hi[F_DIM * K_EIG];            // W^T hi [f][k]
__device__ __nv_bfloat16  g_wt_lo[F_DIM * K_EIG];            // W^T lo [f][k]
__device__ __nv_bfloat16  g_u_hi[(size_t)N_NODES * K_EIG];   // U hi [n][k]
__device__ __nv_bfloat16  g_u_lo[(size_t)N_NODES * K_EIG];   // U lo [n][k]
__device__ __nv_bfloat16  g_x_hi[(size_t)N_NODES * F_DIM];   // X hi [n][f]
__device__ __nv_bfloat16  g_x_lo[(size_t)N_NODES * F_DIM];   // X lo [n][f]

// ---------------- helpers --------------------------------------------------
static __device__ __forceinline__ uint32_t smem_u32(const void* p) {
    uint32_t a;
    asm("{ .reg .u64 t; cvta.to.shared.u64 t, %1; cvt.u32.u64 %0, t; }" : "=r"(a) : "l"(p));
    return a;
}

#define LDSM_X4(r0, r1, r2, r3, addr) \
    asm volatile("ldmatrix.sync.aligned.m8n8.x4.shared.b16 {%0,%1,%2,%3}, [%4];" \
        : "=r"(r0), "=r"(r1), "=r"(r2), "=r"(r3) : "r"(addr))

#define LDSM_X4_T(r0, r1, r2, r3, addr) \
    asm volatile("ldmatrix.sync.aligned.m8n8.x4.trans.shared.b16 {%0,%1,%2,%3}, [%4];" \
        : "=r"(r0), "=r"(r1), "=r"(r2), "=r"(r3) : "r"(addr))

#define MMA_BF16(c0, c1, c2, c3, a0, a1, a2, a3, b0, b1) \
    asm volatile("mma.sync.aligned.m16n8k16.row.col.f32.bf16.bf16.f32 " \
        "{%0,%1,%2,%3}, {%4,%5,%6,%7}, {%8,%9}, {%0,%1,%2,%3};" \
        : "+f"(c0), "+f"(c1), "+f"(c2), "+f"(c3) \
        : "r"(a0), "r"(a1), "r"(a2), "r"(a3), "r"(b0), "r"(b1))

static __device__ __forceinline__ void cp16(uint32_t dst, const void* src, int sz) {
    asm volatile("cp.async.cg.shared.global [%0], [%1], 16, %2;"
                 :: "r"(dst), "l"(src), "r"(sz));
}
#define CP_COMMIT() asm volatile("cp.async.commit_group;" ::: "memory")
#define CP_WAIT1()  asm volatile("cp.async.wait_group 1;"  ::: "memory")
#define CP_WAIT0()  asm volatile("cp.async.wait_group 0;"  ::: "memory")

static __device__ __forceinline__ uint32_t pack_bf2(__nv_bfloat16 a, __nv_bfloat16 b) {
    __nv_bfloat162 t; t.x = a; t.y = b;
    return *reinterpret_cast<uint32_t*>(&t);
}
static __device__ __forceinline__ void split_bf16(float f, __nv_bfloat16& h, __nv_bfloat16& l) {
    h = __float2bfloat16(f);
    l = __float2bfloat16(f - __bfloat162float(h));
}

// ---------------- geometry -------------------------------------------------
// phase1 tiles: [32 node rows][128 cols] bf16, stride 272B (256 data + 16 pad; 272 = 17*16)
#define S1 272
#define T1 (32 * S1)     // 8704
#define B1 (4 * T1)      // 34816: Uhi, Ulo, Xhi, Xlo
#define SMEM1 (3 * B1)   // 104448 (3-buffer ring; 2 CTAs/SM = 204 KB, fits)
#define P1_ITERS  22
#define P1_CHUNK  (P1_ITERS * 32)   // 704
#define P1_CHUNKS 72                // 4 x 72 = 288 CTAs (one wave @ 2/SM)

// phase2 tiles: [128 rows][32 k cols] bf16, PACKED 64B rows + XOR swizzle.
// byte offset of (row, seg16) = row*64 + (seg ^ ((row>>1)&3))*16
//  -> 16B-aligned cp.async dsts, conflict-free ldmatrix (slot index
//     (row&1)*4 + (seg^((row>>1)&3)) is a bijection over row mod 8).
#define T2 (128 * 64)    // 8192
#define B2 (4 * T2)      // 32768: Ahi, Alo, Bhi, Blo
#define SMEM2 (3 * B2)   // 98304 (3-buffer ring; 2 CTAs/SM = 192 KB, fits)
#define NIT2 (K_EIG / 32)  // 16

static __device__ __forceinline__ uint32_t sw2(uint32_t row, uint32_t seg) {
    return row * 64 + ((seg ^ ((row >> 1) & 3)) << 4);
}

// ---------------------------------------------------------------------------
// Kernel 0: zero spec scratch (graph replays re-zero every call)
// ---------------------------------------------------------------------------
__global__ void zero_spec_kernel() {
    int idx = blockIdx.x * blockDim.x + threadIdx.x;
    reinterpret_cast<float4*>(g_spec)[idx] = make_float4(0.f, 0.f, 0.f, 0.f);
}

// ---------------------------------------------------------------------------
// Kernel S: split U and X into hi/lo bf16 (one bandwidth pass)
// ---------------------------------------------------------------------------
__global__ __launch_bounds__(256)
void split_kernel(const float* __restrict__ U, const float* __restrict__ X) {
    const size_t gid = (size_t)blockIdx.x * 256 + threadIdx.x;
    const size_t UN = (size_t)N_NODES * K_EIG / 8;   // 3,200,000
    const float* src;
    __nv_bfloat16 *dhi, *dlo;
    size_t e;
    if (gid < UN) {
        e = gid * 8;
        src = U + e; dhi = g_u_hi + e; dlo = g_u_lo + e;
    } else {
        e = (gid - UN) * 8;
        src = X + e; dhi = g_x_hi + e; dlo = g_x_lo + e;
    }
    float4 v0 = *reinterpret_cast<const float4*>(src);
    float4 v1 = *reinterpret_cast<const float4*>(src + 4);
    __nv_bfloat16 h[8], l[8];
    split_bf16(v0.x, h[0], l[0]); split_bf16(v0.y, h[1], l[1]);
    split_bf16(v0.z, h[2], l[2]); split_bf16(v0.w, h[3], l[3]);
    split_bf16(v1.x, h[4], l[4]); split_bf16(v1.y, h[5], l[5]);
    split_bf16(v1.z, h[6], l[6]); split_bf16(v1.w, h[7], l[7]);
    *reinterpret_cast<uint4*>(dhi) =
        make_uint4(pack_bf2(h[0], h[1]), pack_bf2(h[2], h[3]),
                   pack_bf2(h[4], h[5]), pack_bf2(h[6], h[7]));
    *reinterpret_cast<uint4*>(dlo) =
        make_uint4(pack_bf2(l[0], l[1]), pack_bf2(l[2], l[3]),
                   pack_bf2(l[4], l[5]), pack_bf2(l[6], l[7]));
}

// ---------------------------------------------------------------------------
// Phase 1: spec[k,f] += sum_n U[n,k]*x[n,f]
// smem tiles natural [node][k] / [node][f]; fragments via ldmatrix.trans.
// ---------------------------------------------------------------------------
static __device__ __forceinline__ void p1_issue(uint32_t sb, int buf, int tid,
                                                int k0, int nodebase) {
#pragma unroll
    for (int t = 0; t < 8; t++) {
        const int seg = tid + t * 256;       // 0..2047
        const int tile = seg >> 9;           // 0:Uhi 1:Ulo 2:Xhi 3:Xlo
        const int s = seg & 511;
        const int row = s >> 4, sc = s & 15; // 32 rows x 16 segs of 16B
        const uint32_t dst = sb + buf * B1 + tile * T1 + (uint32_t)row * S1 + sc * 16;
        const int node = nodebase + row;
        const __nv_bfloat16* src;
        if (tile == 0)      src = g_u_hi + (size_t)node * K_EIG + k0 + sc * 8;
        else if (tile == 1) src = g_u_lo + (size_t)node * K_EIG + k0 + sc * 8;
        else if (tile == 2) src = g_x_hi + (size_t)node * F_DIM + sc * 8;
        else                src = g_x_lo + (size_t)node * F_DIM + sc * 8;
        int sz = 16;
        if (node >= N_NODES) { sz = 0; src = g_u_hi; }
        cp16(dst, src, sz);
    }
    CP_COMMIT();
}

static __device__ __forceinline__ void p1_mma(uint32_t base, int wm, int wf,
                                              int lane, float c[2][8][4]) {
#pragma unroll
    for (int ks = 0; ks < 2; ks++) {         // contraction 32 nodes = 2 x kk16
        uint32_t ahi[2][4], alo[2][4];
#pragma unroll
        for (int mi = 0; mi < 2; mi++) {
            const uint32_t row = ks * 16 + (lane & 7) + ((lane >> 4) & 1) * 8;     // node
            const uint32_t col = (wm * 32 + mi * 16 + ((lane >> 3) & 1) * 8) * 2;  // k bytes
            const uint32_t off = row * S1 + col;
            LDSM_X4_T(ahi[mi][0], ahi[mi][1], ahi[mi][2], ahi[mi][3], base + 0 * T1 + off);
            LDSM_X4_T(alo[mi][0], alo[mi][1], alo[mi][2], alo[mi][3], base + 1 * T1 + off);
        }
#pragma unroll
        for (int gp = 0; gp < 4; gp++) {
            const uint32_t row = ks * 16 + (lane & 7) + ((lane >> 3) & 1) * 8;     // node
            const uint32_t col = (wf * 64 + gp * 16 + ((lane >> 4) & 1) * 8) * 2;  // f bytes
            const uint32_t off = row * S1 + col;
            uint32_t bh[4], bl[4];
            LDSM_X4_T(bh[0], bh[1], bh[2], bh[3], base + 2 * T1 + off);
            LDSM_X4_T(bl[0], bl[1], bl[2], bl[3], base + 3 * T1 + off);
#pragma unroll
            for (int mi = 0; mi < 2; mi++) {
#pragma unroll
                for (int gg = 0; gg < 2; gg++) {
                    float* cc = c[mi][gp * 2 + gg];
                    MMA_BF16(cc[0], cc[1], cc[2], cc[3],
                             ahi[mi][0], ahi[mi][1], ahi[mi][2], ahi[mi][3],
                             bh[gg * 2], bh[gg * 2 + 1]);
                    MMA_BF16(cc[0], cc[1], cc[2], cc[3],
                             ahi[mi][0], ahi[mi][1], ahi[mi][2], ahi[mi][3],
                             bl[gg * 2], bl[gg * 2 + 1]);
                    MMA_BF16(cc[0], cc[1], cc[2], cc[3],
                             alo[mi][0], alo[mi][1], alo[mi][2], alo[mi][3],
                             bh[gg * 2], bh[gg * 2 + 1]);
                }
            }
        }
    }
}

__global__ __launch_bounds__(256, 2)
void phase1_mma() {
    extern __shared__ char smem[];
    const uint32_t sb = smem_u32(smem);
    const int tid = threadIdx.x, wid = tid >> 5, lane = tid & 31;
    const int wm = wid >> 1, wf = wid & 1;

    const int k0    = blockIdx.x * 128;
    const int nbase = blockIdx.y * P1_CHUNK;

    float c[2][8][4];
#pragma unroll
    for (int mi = 0; mi < 2; mi++)
#pragma unroll
        for (int g = 0; g < 8; g++)
#pragma unroll
            for (int r = 0; r < 4; r++) c[mi][g][r] = 0.f;

    // 3-buffer ring, 2 groups in flight, ONE sync per chunk.
    p1_issue(sb, 0, tid, k0, nbase);
    p1_issue(sb, 1, tid, k0, nbase + 32);
    int bm = 0;                          // buffer holding chunk 'it'
    for (int it = 0; it < P1_ITERS; it++) {
        if (it == P1_ITERS - 1) { CP_WAIT0(); } else { CP_WAIT1(); }
        __syncthreads();                 // chunk it visible; mma(it-1) done by all
        if (it + 2 < P1_ITERS) {
            int bi = bm + 2; if (bi >= 3) bi -= 3;      // buffer of chunk it-1
            p1_issue(sb, bi, tid, k0, nbase + (it + 2) * 32);
        }
        p1_mma(sb + bm * B1, wm, wf, lane, c);
        if (++bm == 3) bm = 0;
    }

    // reduce into g_spec
#pragma unroll
    for (int mi = 0; mi < 2; mi++) {
        const int k = k0 + wm * 32 + mi * 16 + (lane >> 2);
#pragma unroll
        for (int g = 0; g < 8; g++) {
            const int f = wf * 64 + g * 8 + (lane & 3) * 2;
            atomicAdd(&g_spec[k * F_DIM + f],           c[mi][g][0]);
            atomicAdd(&g_spec[k * F_DIM + f + 1],       c[mi][g][1]);
            atomicAdd(&g_spec[(k + 8) * F_DIM + f],     c[mi][g][2]);
            atomicAdd(&g_spec[(k + 8) * F_DIM + f + 1], c[mi][g][3]);
        }
    }
}

// ---------------------------------------------------------------------------
// Kernel 1.5: Wt[f][k] = split_bf16( g[k] * spec[k][f] )
// ---------------------------------------------------------------------------
__global__ void transpose_scale_kernel(const float* __restrict__ g) {
    __shared__ float tile[32][33];
    const int k0 = blockIdx.x * 32, f0 = blockIdx.y * 32;
    const int tx = threadIdx.x, ty = threadIdx.y;
#pragma unroll
    for (int i = 0; i < 4; i++) {
        const int k = k0 + ty + 8 * i;
        tile[ty + 8 * i][tx] = g_spec[k * F_DIM + f0 + tx] * g[k];
    }
    __syncthreads();
#pragma unroll
    for (int i = 0; i < 4; i++) {
        const int f = f0 + ty + 8 * i;
        const int k = k0 + tx;
        const float v = tile[tx][ty + 8 * i];
        __nv_bfloat16 h = __float2bfloat16(v);
        g_wt_hi[f * K_EIG + k] = h;
        g_wt_lo[f * K_EIG + k] = __float2bfloat16(v - __bfloat162float(h));
    }
}

// ---------------------------------------------------------------------------
// Phase 2: out[n,f] = relu( sum_k U[n,k] * Wt[f,k] )  — K-major, swizzled smem.
// ---------------------------------------------------------------------------
static __device__ __forceinline__ void p2_issue(uint32_t sb, int buf, int tid,
                                                int n0, int kc) {
#pragma unroll
    for (int t = 0; t < 8; t++) {
        const int seg = tid + t * 256;       // 0..2047
        const int tile = seg >> 9;           // 0:Ahi 1:Alo 2:Bhi 3:Blo
        const int s = seg & 511;
        const int row = s >> 2, sc = s & 3;  // 128 rows x 4 segs of 16B
        const uint32_t dst = sb + buf * B2 + tile * T2 + sw2((uint32_t)row, (uint32_t)sc);
        const __nv_bfloat16* src;
        int sz = 16;
        if (tile < 2) {
            const int node = n0 + row;
            src = (tile == 0 ? g_u_hi : g_u_lo) + (size_t)node * K_EIG + kc + sc * 8;
            if (node >= N_NODES) { sz = 0; src = g_u_hi; }
        } else {
            src = (tile == 2 ? g_wt_hi : g_wt_lo) + (size_t)row * K_EIG + kc + sc * 8;
        }
        cp16(dst, src, sz);
    }
    CP_COMMIT();
}

static __device__ __forceinline__ void p2_mma(uint32_t base, int wm, int wf,
                                              int lane, float c[2][8][4]) {
#pragma unroll
    for (int ks = 0; ks < 2; ks++) {         // contraction 32 k = 2 x kk16
        uint32_t ahi[2][4], alo[2][4];
#pragma unroll
        for (int mi = 0; mi < 2; mi++) {
            const uint32_t row = wm * 32 + mi * 16 + (lane & 7) + ((lane >> 3) & 1) * 8;
            const uint32_t off = sw2(row, ks * 2 + (lane >> 4));
            LDSM_X4(ahi[mi][0], ahi[mi][1], ahi[mi][2], ahi[mi][3], base + 0 * T2 + off);
            LDSM_X4(alo[mi][0], alo[mi][1], alo[mi][2], alo[mi][3], base + 1 * T2 + off);
        }
#pragma unroll
        for (int gp = 0; gp < 4; gp++) {
            const uint32_t row = wf * 64 + gp * 16 + (lane & 7) + ((lane >> 4) & 1) * 8;
            const uint32_t off = sw2(row, ks * 2 + ((lane >> 3) & 1));
            uint32_t bh[4], bl[4];
            LDSM_X4(bh[0], bh[1], bh[2], bh[3], base + 2 * T2 + off);
            LDSM_X4(bl[0], bl[1], bl[2], bl[3], base + 3 * T2 + off);
#pragma unroll
            for (int mi = 0; mi < 2; mi++) {
#pragma unroll
                for (int gg = 0; gg < 2; gg++) {
                    float* cc = c[mi][gp * 2 + gg];
                    MMA_BF16(cc[0], cc[1], cc[2], cc[3],
                             ahi[mi][0], ahi[mi][1], ahi[mi][2], ahi[mi][3],
                             bh[gg * 2], bh[gg * 2 + 1]);
                    MMA_BF16(cc[0], cc[1], cc[2], cc[3],
                             ahi[mi][0], ahi[mi][1], ahi[mi][2], ahi[mi][3],
                             bl[gg * 2], bl[gg * 2 + 1]);
                    MMA_BF16(cc[0], cc[1], cc[2], cc[3],
                             alo[mi][0], alo[mi][1], alo[mi][2], alo[mi][3],
                             bh[gg * 2], bh[gg * 2 + 1]);
                }
            }
        }
    }
}

__global__ __launch_bounds__(256, 2)
void phase2_mma(float* __restrict__ out) {
    extern __shared__ char smem[];
    const uint32_t sb = smem_u32(smem);
    const int tid = threadIdx.x, wid = tid >> 5, lane = tid & 31;
    const int wm = wid >> 1, wf = wid & 1;

    const int n0 = blockIdx.x * 128;

    float c[2][8][4];
#pragma unroll
    for (int mi = 0; mi < 2; mi++)
#pragma unroll
        for (int g = 0; g < 8; g++)
#pragma unroll
            for (int r = 0; r < 4; r++) c[mi][g][r] = 0.f;

    p2_issue(sb, 0, tid, n0, 0);
    p2_issue(sb, 1, tid, n0, 32);
    int bm = 0;
    for (int it = 0; it < NIT2; it++) {
        if (it == NIT2 - 1) { CP_WAIT0(); } else { CP_WAIT1(); }
        __syncthreads();
        if (it + 2 < NIT2) {
            int bi = bm + 2; if (bi >= 3) bi -= 3;
            p2_issue(sb, bi, tid, n0, (it + 2) * 32);
        }
        p2_mma(sb + bm * B2, wm, wf, lane, c);
        if (++bm == 3) bm = 0;
    }

    // relu + store
#pragma unroll
    for (int mi = 0; mi < 2; mi++) {
        const int node = n0 + wm * 32 + mi * 16 + (lane >> 2);
#pragma unroll
        for (int g = 0; g < 8; g++) {
            const int f = wf * 64 + g * 8 + (lane & 3) * 2;
            if (node < N_NODES) {
                float2 v0;
                v0.x = fmaxf(c[mi][g][0], 0.f);
                v0.y = fmaxf(c[mi][g][1], 0.f);
                *reinterpret_cast<float2*>(out + (size_t)node * F_DIM + f) = v0;
            }
            if (node + 8 < N_NODES) {
                float2 v1;
                v1.x = fmaxf(c[mi][g][2], 0.f);
                v1.y = fmaxf(c[mi][g][3], 0.f);
                *reinterpret_cast<float2*>(out + (size_t)(node + 8) * F_DIM + f) = v1;
            }
        }
    }
}

// ---------------------------------------------------------------------------
// Launch
// ---------------------------------------------------------------------------
extern "C" void kernel_launch(void* const* d_in, const int* in_sizes, int n_in,
                              void* d_out, int out_size) {
    const float* U = (const float*)d_in[0];   // eigenvectors [N, K]
    const float* g = (const float*)d_in[1];   // spectral_filters [K]
    const float* X = (const float*)d_in[2];   // x [N, F]
    float* out = (float*)d_out;               // [N, F]

    cudaFuncSetAttribute(phase1_mma, cudaFuncAttributeMaxDynamicSharedMemorySize, SMEM1);
    cudaFuncSetAttribute(phase2_mma, cudaFuncAttributeMaxDynamicSharedMemorySize, SMEM2);

    zero_spec_kernel<<<64, 256>>>();

    split_kernel<<<15625, 256>>>(U, X);

    phase1_mma<<<dim3(4, P1_CHUNKS), 256, SMEM1>>>();

    transpose_scale_kernel<<<dim3(K_EIG / 32, F_DIM / 32), dim3(32, 8)>>>(g);

    phase2_mma<<<(N_NODES + 127) / 128, 256, SMEM2>>>(out);
}

// round 11
// speedup vs baseline: 3.8779x; 1.1815x over previous
#include <cuda_runtime.h>
#include <cuda_bf16.h>
#include <cstdint>

#define N_NODES 50000
#define K_EIG   512
#define F_DIM   128

// ---------------- device scratch (static; no runtime allocation) ----------
__device__ float          g_spec[K_EIG * F_DIM];             // fp32 spec [k][f]
__device__ __nv_bfloat16  g_wt_hi[F_DIM * K_EIG];            // W^T hi [f][k]
__device__ __nv_bfloat16  g_wt_lo[F_DIM * K_EIG];            // W^T lo [f][k]

// ---------------- helpers --------------------------------------------------
static __device__ __forceinline__ uint32_t smem_u32(const void* p) {
    uint32_t a;
    asm("{ .reg .u64 t; cvta.to.shared.u64 t, %1; cvt.u32.u64 %0, t; }" : "=r"(a) : "l"(p));
    return a;
}

#define LDSM_X4(r0, r1, r2, r3, addr) \
    asm volatile("ldmatrix.sync.aligned.m8n8.x4.shared.b16 {%0,%1,%2,%3}, [%4];" \
        : "=r"(r0), "=r"(r1), "=r"(r2), "=r"(r3) : "r"(addr))

#define LDSM_X4_T(r0, r1, r2, r3, addr) \
    asm volatile("ldmatrix.sync.aligned.m8n8.x4.trans.shared.b16 {%0,%1,%2,%3}, [%4];" \
        : "=r"(r0), "=r"(r1), "=r"(r2), "=r"(r3) : "r"(addr))

#define MMA_BF16(c0, c1, c2, c3, a0, a1, a2, a3, b0, b1) \
    asm volatile("mma.sync.aligned.m16n8k16.row.col.f32.bf16.bf16.f32 " \
        "{%0,%1,%2,%3}, {%4,%5,%6,%7}, {%8,%9}, {%0,%1,%2,%3};" \
        : "+f"(c0), "+f"(c1), "+f"(c2), "+f"(c3) \
        : "r"(a0), "r"(a1), "r"(a2), "r"(a3), "r"(b0), "r"(b1))

static __device__ __forceinline__ void cp16(uint32_t dst, const void* src, int sz) {
    asm volatile("cp.async.cg.shared.global [%0], [%1], 16, %2;"
                 :: "r"(dst), "l"(src), "r"(sz));
}
#define CP_COMMIT() asm volatile("cp.async.commit_group;" ::: "memory")
#define CP_WAIT1()  asm volatile("cp.async.wait_group 1;"  ::: "memory")
#define CP_WAIT0()  asm volatile("cp.async.wait_group 0;"  ::: "memory")

static __device__ __forceinline__ uint32_t pack_bf2(__nv_bfloat16 a, __nv_bfloat16 b) {
    __nv_bfloat162 t; t.x = a; t.y = b;
    return *reinterpret_cast<uint32_t*>(&t);
}
static __device__ __forceinline__ void split_bf16(float f, __nv_bfloat16& h, __nv_bfloat16& l) {
    h = __float2bfloat16(f);
    l = __float2bfloat16(f - __bfloat162float(h));
}
// split 8 floats (2 float4) -> hi uint4 + lo uint4
static __device__ __forceinline__ void split8(float4 v0, float4 v1, uint4& hi, uint4& lo) {
    __nv_bfloat16 h[8], l[8];
    split_bf16(v0.x, h[0], l[0]); split_bf16(v0.y, h[1], l[1]);
    split_bf16(v0.z, h[2], l[2]); split_bf16(v0.w, h[3], l[3]);
    split_bf16(v1.x, h[4], l[4]); split_bf16(v1.y, h[5], l[5]);
    split_bf16(v1.z, h[6], l[6]); split_bf16(v1.w, h[7], l[7]);
    hi = make_uint4(pack_bf2(h[0], h[1]), pack_bf2(h[2], h[3]),
                    pack_bf2(h[4], h[5]), pack_bf2(h[6], h[7]));
    lo = make_uint4(pack_bf2(l[0], l[1]), pack_bf2(l[2], l[3]),
                    pack_bf2(l[4], l[5]), pack_bf2(l[6], l[7]));
}

// ---------------- geometry -------------------------------------------------
// phase1: chunk = 32 nodes. fp32 stages (U,X each 32x128 fp32 = 16 KB), ring 2.
// bf16 block: 4 tiles [32 rows][128 cols] bf16 @ stride 272, single-buffered.
#define S1     272
#define T1     (32 * S1)          // 8704
#define F1     16384              // one fp32 operand stage
#define FS1    (2 * F1)           // 32768 per ring slot (U + X)
#define OFFB1  (2 * FS1)          // 65536: bf16 block [Uhi][Ulo][Xhi][Xlo]
#define SMEM1  (OFFB1 + 4 * T1)   // 100352
#define P1_ITERS  22
#define P1_CHUNK  (P1_ITERS * 32) // 704
#define P1_CHUNKS 72              // 4 x 72 = 288 CTAs

// phase2: chunk = 32 k. A fp32 stage 128x32 fp32 = 16 KB, ring 2.
// B (Wt hi+lo) bf16 16 KB/stage, ring 3. A bf16 hi/lo 8 KB each, single.
// bf16 tiles packed 64B rows + XOR swizzle (16B-aligned, conflict-free).
#define T2     (128 * 64)         // 8192
#define OFFB2  (2 * 16384)        // 32768: B ring (3 x 16384)
#define OFFA2  (OFFB2 + 3 * 16384)// 81920: A bf16 [hi][lo]
#define SMEM2  (OFFA2 + 2 * T2)   // 98304
#define NIT2   (K_EIG / 32)       // 16

static __device__ __forceinline__ uint32_t sw2(uint32_t row, uint32_t seg) {
    return row * 64 + ((seg ^ ((row >> 1) & 3)) << 4);
}

// ---------------------------------------------------------------------------
// Kernel 0: zero spec scratch (graph replays re-zero every call)
// ---------------------------------------------------------------------------
__global__ void zero_spec_kernel() {
    int idx = blockIdx.x * blockDim.x + threadIdx.x;
    reinterpret_cast<float4*>(g_spec)[idx] = make_float4(0.f, 0.f, 0.f, 0.f);
}

// ---------------------------------------------------------------------------
// Phase 1: spec[k,f] += sum_n U[n,k]*x[n,f]
// ---------------------------------------------------------------------------
static __device__ __forceinline__ void p1_issue(uint32_t sb, int slot, int tid,
                                                const float* U, const float* X,
                                                int k0, int nodebase) {
#pragma unroll
    for (int t = 0; t < 8; t++) {
        const int seg = tid + t * 256;        // 0..2047
        const int tile = seg >> 10;           // 0:U 1:X
        const int s = seg & 1023;
        const int row = s >> 5, sc = s & 31;  // 32 rows x 32 segs of 16B
        const uint32_t dst = sb + slot * FS1 + tile * F1 + (uint32_t)row * 512 + sc * 16;
        const int node = nodebase + row;
        const float* src = tile ? (X + (size_t)node * F_DIM + sc * 4)
                                : (U + (size_t)node * K_EIG + k0 + sc * 4);
        int sz = 16;
        if (node >= N_NODES) { sz = 0; src = (const float*)g_spec; }
        cp16(dst, src, sz);
    }
    CP_COMMIT();
}

static __device__ __forceinline__ void p1_cvt(char* smem, int slot, int tid) {
#pragma unroll
    for (int t = 0; t < 4; t++) {
        const int task = tid + t * 256;       // 0..1023
        const int tile = task >> 9;           // 0:U->A 1:X->B
        const int s = task & 511;
        const int row = s >> 4, seg8 = s & 15;
        const float4* p = reinterpret_cast<const float4*>(
            smem + slot * FS1 + tile * F1 + (uint32_t)row * 512 + seg8 * 32);
        uint4 hi, lo;
        split8(p[0], p[1], hi, lo);
        const uint32_t off = (uint32_t)row * S1 + seg8 * 16;
        char* base = smem + OFFB1 + (tile * 2) * T1;
        *reinterpret_cast<uint4*>(base + off) = hi;
        *reinterpret_cast<uint4*>(base + T1 + off) = lo;
    }
}

static __device__ __forceinline__ void p1_mma(uint32_t base, int wm, int wf,
                                              int lane, float c[2][8][4]) {
#pragma unroll
    for (int ks = 0; ks < 2; ks++) {          // contraction 32 nodes = 2 x kk16
        uint32_t ahi[2][4], alo[2][4];
#pragma unroll
        for (int mi = 0; mi < 2; mi++) {
            const uint32_t row = ks * 16 + (lane & 7) + ((lane >> 4) & 1) * 8;     // node
            const uint32_t col = (wm * 32 + mi * 16 + ((lane >> 3) & 1) * 8) * 2;  // k bytes
            const uint32_t off = row * S1 + col;
            LDSM_X4_T(ahi[mi][0], ahi[mi][1], ahi[mi][2], ahi[mi][3], base + 0 * T1 + off);
            LDSM_X4_T(alo[mi][0], alo[mi][1], alo[mi][2], alo[mi][3], base + 1 * T1 + off);
        }
#pragma unroll
        for (int gp = 0; gp < 4; gp++) {
            const uint32_t row = ks * 16 + (lane & 7) + ((lane >> 3) & 1) * 8;     // node
            const uint32_t col = (wf * 64 + gp * 16 + ((lane >> 4) & 1) * 8) * 2;  // f bytes
            const uint32_t off = row * S1 + col;
            uint32_t bh[4], bl[4];
            LDSM_X4_T(bh[0], bh[1], bh[2], bh[3], base + 2 * T1 + off);
            LDSM_X4_T(bl[0], bl[1], bl[2], bl[3], base + 3 * T1 + off);
#pragma unroll
            for (int mi = 0; mi < 2; mi++) {
#pragma unroll
                for (int gg = 0; gg < 2; gg++) {
                    float* cc = c[mi][gp * 2 + gg];
                    MMA_BF16(cc[0], cc[1], cc[2], cc[3],
                             ahi[mi][0], ahi[mi][1], ahi[mi][2], ahi[mi][3],
                             bh[gg * 2], bh[gg * 2 + 1]);
                    MMA_BF16(cc[0], cc[1], cc[2], cc[3],
                             ahi[mi][0], ahi[mi][1], ahi[mi][2], ahi[mi][3],
                             bl[gg * 2], bl[gg * 2 + 1]);
                    MMA_BF16(cc[0], cc[1], cc[2], cc[3],
                             alo[mi][0], alo[mi][1], alo[mi][2], alo[mi][3],
                             bh[gg * 2], bh[gg * 2 + 1]);
                }
            }
        }
    }
}

__global__ __launch_bounds__(256, 2)
void phase1_mma(const float* __restrict__ U, const float* __restrict__ X) {
    extern __shared__ char smem[];
    const uint32_t sb = smem_u32(smem);
    const int tid = threadIdx.x, wid = tid >> 5, lane = tid & 31;
    const int wm = wid >> 1, wf = wid & 1;

    const int k0    = blockIdx.x * 128;
    const int nbase = blockIdx.y * P1_CHUNK;

    float c[2][8][4];
#pragma unroll
    for (int mi = 0; mi < 2; mi++)
#pragma unroll
        for (int g = 0; g < 8; g++)
#pragma unroll
            for (int r = 0; r < 4; r++) c[mi][g][r] = 0.f;

    // fp32 ring-2; structure: wait -> sync -> cvt -> sync -> issue(it+2) -> mma
    p1_issue(sb, 0, tid, U, X, k0, nbase);
    p1_issue(sb, 1, tid, U, X, k0, nbase + 32);
    for (int it = 0; it < P1_ITERS; it++) {
        if (it == P1_ITERS - 1) { CP_WAIT0(); } else { CP_WAIT1(); }
        __syncthreads();                      // fp32 chunk it visible; mma(it-1) done
        p1_cvt(smem, it & 1, tid);
        __syncthreads();                      // bf16 tiles visible; fp32 slot reusable
        if (it + 2 < P1_ITERS)
            p1_issue(sb, it & 1, tid, U, X, k0, nbase + (it + 2) * 32);
        p1_mma(sb + OFFB1, wm, wf, lane, c);
    }

    // reduce into g_spec
#pragma unroll
    for (int mi = 0; mi < 2; mi++) {
        const int k = k0 + wm * 32 + mi * 16 + (lane >> 2);
#pragma unroll
        for (int g = 0; g < 8; g++) {
            const int f = wf * 64 + g * 8 + (lane & 3) * 2;
            atomicAdd(&g_spec[k * F_DIM + f],           c[mi][g][0]);
            atomicAdd(&g_spec[k * F_DIM + f + 1],       c[mi][g][1]);
            atomicAdd(&g_spec[(k + 8) * F_DIM + f],     c[mi][g][2]);
            atomicAdd(&g_spec[(k + 8) * F_DIM + f + 1], c[mi][g][3]);
        }
    }
}

// ---------------------------------------------------------------------------
// Kernel 1.5: Wt[f][k] = split_bf16( g[k] * spec[k][f] )
// ---------------------------------------------------------------------------
__global__ void transpose_scale_kernel(const float* __restrict__ g) {
    __shared__ float tile[32][33];
    const int k0 = blockIdx.x * 32, f0 = blockIdx.y * 32;
    const int tx = threadIdx.x, ty = threadIdx.y;
#pragma unroll
    for (int i = 0; i < 4; i++) {
        const int k = k0 + ty + 8 * i;
        tile[ty + 8 * i][tx] = g_spec[k * F_DIM + f0 + tx] * g[k];
    }
    __syncthreads();
#pragma unroll
    for (int i = 0; i < 4; i++) {
        const int f = f0 + ty + 8 * i;
        const int k = k0 + tx;
        const float v = tile[tx][ty + 8 * i];
        __nv_bfloat16 h = __float2bfloat16(v);
        g_wt_hi[f * K_EIG + k] = h;
        g_wt_lo[f * K_EIG + k] = __float2bfloat16(v - __bfloat162float(h));
    }
}

// ---------------------------------------------------------------------------
// Phase 2: out[n,f] = relu( sum_k U[n,k] * Wt[f,k] )
// ---------------------------------------------------------------------------
static __device__ __forceinline__ void p2_issue(uint32_t sb, int it, int tid,
                                                const float* U, int n0, int kc) {
    const int aslot = it & 1, bslot = it % 3;
#pragma unroll
    for (int t = 0; t < 8; t++) {
        const int seg = tid + t * 256;        // 0..2047; first 1024 A fp32, rest B bf16
        uint32_t dst;
        const void* src;
        int sz = 16;
        if (seg < 1024) {
            const int row = seg >> 3, sc = seg & 7;   // 128 rows x 8 segs
            dst = sb + aslot * 16384 + (uint32_t)row * 128 + sc * 16;
            const int node = n0 + row;
            src = U + (size_t)node * K_EIG + kc + sc * 4;
            if (node >= N_NODES) { sz = 0; src = g_spec; }
        } else {
            const int s = seg - 1024;          // 0..1023
            const int tile = s >> 9;           // 0:hi 1:lo
            const int r = s & 511;
            const int row = r >> 2, sc = r & 3;
            dst = sb + OFFB2 + bslot * 16384 + tile * T2 + sw2((uint32_t)row, (uint32_t)sc);
            src = (tile ? g_wt_lo : g_wt_hi) + (size_t)row * K_EIG + kc + sc * 8;
        }
        cp16(dst, src, sz);
    }
    CP_COMMIT();
}

static __device__ __forceinline__ void p2_cvt(char* smem, int slot, int tid) {
#pragma unroll
    for (int t = 0; t < 2; t++) {
        const int task = tid + t * 256;       // 0..511
        const int row = task >> 2, seg8 = task & 3;
        const float4* p = reinterpret_cast<const float4*>(
            smem + slot * 16384 + (uint32_t)row * 128 + seg8 * 32);
        uint4 hi, lo;
        split8(p[0], p[1], hi, lo);
        const uint32_t off = sw2((uint32_t)row, (uint32_t)seg8);
        *reinterpret_cast<uint4*>(smem + OFFA2 + off) = hi;
        *reinterpret_cast<uint4*>(smem + OFFA2 + T2 + off) = lo;
    }
}

static __device__ __forceinline__ void p2_mma(uint32_t baseA, uint32_t baseB,
                                              int wm, int wf, int lane,
                                              float c[2][8][4]) {
#pragma unroll
    for (int ks = 0; ks < 2; ks++) {          // contraction 32 k = 2 x kk16
        uint32_t ahi[2][4], alo[2][4];
#pragma unroll
        for (int mi = 0; mi < 2; mi++) {
            const uint32_t row = wm * 32 + mi * 16 + (lane & 7) + ((lane >> 3) & 1) * 8;
            const uint32_t off = sw2(row, ks * 2 + (lane >> 4));
            LDSM_X4(ahi[mi][0], ahi[mi][1], ahi[mi][2], ahi[mi][3], baseA + off);
            LDSM_X4(alo[mi][0], alo[mi][1], alo[mi][2], alo[mi][3], baseA + T2 + off);
        }
#pragma unroll
        for (int gp = 0; gp < 4; gp++) {
            const uint32_t row = wf * 64 + gp * 16 + (lane & 7) + ((lane >> 4) & 1) * 8;
            const uint32_t off = sw2(row, ks * 2 + ((lane >> 3) & 1));
            uint32_t bh[4], bl[4];
            LDSM_X4(bh[0], bh[1], bh[2], bh[3], baseB + off);
            LDSM_X4(bl[0], bl[1], bl[2], bl[3], baseB + T2 + off);
#pragma unroll
            for (int mi = 0; mi < 2; mi++) {
#pragma unroll
                for (int gg = 0; gg < 2; gg++) {
                    float* cc = c[mi][gp * 2 + gg];
                    MMA_BF16(cc[0], cc[1], cc[2], cc[3],
                             ahi[mi][0], ahi[mi][1], ahi[mi][2], ahi[mi][3],
                             bh[gg * 2], bh[gg * 2 + 1]);
                    MMA_BF16(cc[0], cc[1], cc[2], cc[3],
                             ahi[mi][0], ahi[mi][1], ahi[mi][2], ahi[mi][3],
                             bl[gg * 2], bl[gg * 2 + 1]);
                    MMA_BF16(cc[0], cc[1], cc[2], cc[3],
                             alo[mi][0], alo[mi][1], alo[mi][2], alo[mi][3],
                             bh[gg * 2], bh[gg * 2 + 1]);
                }
            }
        }
    }
}

__global__ __launch_bounds__(256, 2)
void phase2_mma(const float* __restrict__ U, float* __restrict__ out) {
    extern __shared__ char smem[];
    const uint32_t sb = smem_u32(smem);
    const int tid = threadIdx.x, wid = tid >> 5, lane = tid & 31;
    const int wm = wid >> 1, wf = wid & 1;

    const int n0 = blockIdx.x * 128;

    float c[2][8][4];
#pragma unroll
    for (int mi = 0; mi < 2; mi++)
#pragma unroll
        for (int g = 0; g < 8; g++)
#pragma unroll
            for (int r = 0; r < 4; r++) c[mi][g][r] = 0.f;

    p2_issue(sb, 0, tid, U, n0, 0);
    p2_issue(sb, 1, tid, U, n0, 32);
    for (int it = 0; it < NIT2; it++) {
        if (it == NIT2 - 1) { CP_WAIT0(); } else { CP_WAIT1(); }
        __syncthreads();                      // chunk it visible; mma(it-1) done
        p2_cvt(smem, it & 1, tid);
        __syncthreads();                      // A bf16 visible; A fp32 slot reusable
        if (it + 2 < NIT2)
            p2_issue(sb, it + 2, tid, U, n0, (it + 2) * 32);
        p2_mma(sb + OFFA2, sb + OFFB2 + (it % 3) * 16384, wm, wf, lane, c);
    }

    // relu + store
#pragma unroll
    for (int mi = 0; mi < 2; mi++) {
        const int node = n0 + wm * 32 + mi * 16 + (lane >> 2);
#pragma unroll
        for (int g = 0; g < 8; g++) {
            const int f = wf * 64 + g * 8 + (lane & 3) * 2;
            if (node < N_NODES) {
                float2 v0;
                v0.x = fmaxf(c[mi][g][0], 0.f);
                v0.y = fmaxf(c[mi][g][1], 0.f);
                *reinterpret_cast<float2*>(out + (size_t)node * F_DIM + f) = v0;
            }
            if (node + 8 < N_NODES) {
                float2 v1;
                v1.x = fmaxf(c[mi][g][2], 0.f);
                v1.y = fmaxf(c[mi][g][3], 0.f);
                *reinterpret_cast<float2*>(out + (size_t)(node + 8) * F_DIM + f) = v1;
            }
        }
    }
}

// ---------------------------------------------------------------------------
// Launch
// ---------------------------------------------------------------------------
extern "C" void kernel_launch(void* const* d_in, const int* in_sizes, int n_in,
                              void* d_out, int out_size) {
    const float* U = (const float*)d_in[0];   // eigenvectors [N, K]
    const float* g = (const float*)d_in[1];   // spectral_filters [K]
    const float* X = (const float*)d_in[2];   // x [N, F]
    float* out = (float*)d_out;               // [N, F]

    cudaFuncSetAttribute(phase1_mma, cudaFuncAttributeMaxDynamicSharedMemorySize, SMEM1);
    cudaFuncSetAttribute(phase2_mma, cudaFuncAttributeMaxDynamicSharedMemorySize, SMEM2);

    zero_spec_kernel<<<64, 256>>>();

    phase1_mma<<<dim3(4, P1_CHUNKS), 256, SMEM1>>>(U, X);

    transpose_scale_kernel<<<dim3(K_EIG / 32, F_DIM / 32), dim3(32, 8)>>>(g);

    phase2_mma<<<(N_NODES + 127) / 128, 256, SMEM2>>>(U, out);
}